// round 12
// baseline (speedup 1.0000x reference)
#include <cuda_runtime.h>
#include <cuda_fp16.h>
#include <mma.h>
using namespace nvcuda;

#define NN 50000          // nodes per type
#define NE 1600000        // edges per edge type
#define CIN 11
#define HD 64
#define CAP 128           // max in-degree bucket (Poisson(32): P(>=128) ~ e^-81)
#define N16 (NN*16)
#define N64 (NN*64)

// ---------------- scratch (device globals; no allocation) ----------------
// g_cnt is zero at module load and re-zeroed by gemm2's tail each replay.
__device__ int            g_cnt[4][NN];       // per-edge-type in-degree
__device__ unsigned short g_col[4][NN*CAP];   // bucketed source ids (ushort)
__device__ __half g_x16[2][N16];        // fp16 x padded to 16-half rows
__device__ __half g_agg1[4][N16];       // layer-1 MEANS (fp16)
__device__ __half g_h1s16[N64], g_h1p16[N64];    // layer-1 activations (fp16)
__device__ __half g_agg2[4][N64];       // layer-2 MEANS (fp16)
__device__ __half g_wb1[2][48*64];      // fp16 layer-1 weights: 3 segs x 16 x 64
__device__ __half g_wb2[2][192*64];     // fp16 layer-2 weights: 3 segs x 64 x 64
__device__ float  g_b1[2][HD], g_b2[2][HD];   // bias pair sums

// ---------------- fused placement + prep (independent block ranges) --------
#define NE8 (NE/8)
#define EBLK8 ((NE8 + 255) / 256)
#define PBLK (4*EBLK8)
// prep ranges
#define R1 (2*N16)         // xpad
#define R2 (2*48*64)       // wb1
#define R3 (2*192*64)      // wb2
#define R4 (2*2*HD)        // bias pairs
#define RTOT2 (R1+R2+R3+R4)
#define QBLK ((RTOT2 + 255)/256)

__global__ void prep_place_kernel(const float* __restrict__ xs, const float* __restrict__ xp,
                                  const float* __restrict__ w1l, const float* __restrict__ w1r,
                                  const float* __restrict__ w2l, const float* __restrict__ w2r,
                                  const float* __restrict__ b1l, const float* __restrict__ b2l,
                                  const int* __restrict__ e0, const int* __restrict__ e1,
                                  const int* __restrict__ e2, const int* __restrict__ e3) {
    if (blockIdx.x < PBLK) {
        // ---- edge placement (8 edges/thread) ----
        int t = blockIdx.x / EBLK8;
        int p = (blockIdx.x - t*EBLK8)*blockDim.x + threadIdx.x;
        if (p >= NE8) return;
        const int* ei = (t==0) ? e0 : (t==1) ? e1 : (t==2) ? e2 : e3;
        int4 sa = *(const int4*)(ei + 8*p);
        int4 sb = *(const int4*)(ei + 8*p + 4);
        int4 da = *(const int4*)(ei + NE + 8*p);
        int4 db = *(const int4*)(ei + NE + 8*p + 4);
        int* cnt = g_cnt[t];
        unsigned short* col = g_col[t];
        int pos;
        pos = atomicAdd(&cnt[da.x], 1); if (pos < CAP) col[(long)da.x*CAP + pos] = (unsigned short)sa.x;
        pos = atomicAdd(&cnt[da.y], 1); if (pos < CAP) col[(long)da.y*CAP + pos] = (unsigned short)sa.y;
        pos = atomicAdd(&cnt[da.z], 1); if (pos < CAP) col[(long)da.z*CAP + pos] = (unsigned short)sa.z;
        pos = atomicAdd(&cnt[da.w], 1); if (pos < CAP) col[(long)da.w*CAP + pos] = (unsigned short)sa.w;
        pos = atomicAdd(&cnt[db.x], 1); if (pos < CAP) col[(long)db.x*CAP + pos] = (unsigned short)sb.x;
        pos = atomicAdd(&cnt[db.y], 1); if (pos < CAP) col[(long)db.y*CAP + pos] = (unsigned short)sb.y;
        pos = atomicAdd(&cnt[db.z], 1); if (pos < CAP) col[(long)db.z*CAP + pos] = (unsigned short)sb.z;
        pos = atomicAdd(&cnt[db.w], 1); if (pos < CAP) col[(long)db.w*CAP + pos] = (unsigned short)sb.w;
        return;
    }
    int i = (blockIdx.x - PBLK)*blockDim.x + threadIdx.x;
    if (i < R1) {
        int half_ = i / N16;
        int j = i - half_*N16;
        int node = j >> 4, c = j & 15;
        const float* x = half_ ? xp : xs;
        ((__half*)g_x16)[i] = (c < CIN) ? __float2half_rn(x[node*CIN + c]) : __half(0.f);
        return;
    }
    i -= R1;
    if (i < R2) {
        int ty = i / 3072;
        int j = i - ty*3072;
        int r = j >> 6, c = j & 63;
        int seg = r >> 4, k = r & 15;
        float v = 0.f;
        if (k < CIN) {
            if (seg < 2) v = w1l[(seg*2 + ty)*CIN*HD + k*HD + c];
            else         v = w1r[ty*CIN*HD + k*HD + c] + w1r[(2+ty)*CIN*HD + k*HD + c];
        }
        g_wb1[ty][r*64 + c] = __float2half_rn(v);
        return;
    }
    i -= R2;
    if (i < R3) {
        int ty = i / 12288;
        int j = i - ty*12288;
        int r = j >> 6, c = j & 63;
        int seg = r >> 6, k = r & 63;
        float v;
        if (seg < 2) v = w2l[(seg*2 + ty)*HD*HD + k*HD + c];
        else         v = w2r[ty*HD*HD + k*HD + c] + w2r[(2+ty)*HD*HD + k*HD + c];
        g_wb2[ty][r*64 + c] = __float2half_rn(v);
        return;
    }
    i -= R3;
    if (i < R4) {
        int which = i >> 7;
        int ty = (i >> 6) & 1;
        int c = i & 63;
        if (which == 0) g_b1[ty][c] = b1l[ty*HD + c] + b1l[(2+ty)*HD + c];
        else            g_b2[ty][c] = b2l[ty*HD + c] + b2l[(2+ty)*HD + c];
    }
}

// ---------------- layer-1 gather (fp16, 16 lanes/node, 2B, unroll 8) -------
__global__ void gather1_kernel() {
    int gid = blockIdx.x*16 + (threadIdx.x >> 4);
    int lane = threadIdx.x & 15;
    if (gid >= 4*NN) return;
    int t = gid / NN, n = gid - t*NN;
    const __half* src = (t < 2) ? g_x16[0] : g_x16[1];
    int cnt = g_cnt[t][n];
    int deg = min(cnt, CAP);
    const unsigned short* col = g_col[t] + (long)n*CAP;
    float acc = 0.f;
    int e = 0;
    int nd8 = deg & ~7;
    for (; e < nd8; e += 8) {
        uint4 cw = *(const uint4*)(col + e);
        int s[8];
        s[0] = cw.x & 0xffff; s[1] = cw.x >> 16;
        s[2] = cw.y & 0xffff; s[3] = cw.y >> 16;
        s[4] = cw.z & 0xffff; s[5] = cw.z >> 16;
        s[6] = cw.w & 0xffff; s[7] = cw.w >> 16;
        __half v[8];
#pragma unroll
        for (int q = 0; q < 8; q++)
            v[q] = src[(long)s[q]*16 + lane];
#pragma unroll
        for (int q = 0; q < 8; q++)
            acc += __half2float(v[q]);
    }
    for (; e < deg; e++) {
        acc += __half2float(src[(long)col[e]*16 + lane]);
    }
    float inv = 1.f / (float)max(cnt, 1);
    g_agg1[t][(long)n*16 + lane] = __float2half_rn(acc*inv);
}

// ---------------- layer-2 gather (fp16, 32 lanes/node = 1 warp, 4B) --------
__global__ void gather2_kernel() {
    int gid = blockIdx.x*8 + (threadIdx.x >> 5);
    int lane = threadIdx.x & 31;
    if (gid >= 4*NN) return;
    int t = gid / NN, n = gid - t*NN;
    const __half* src = (t < 2) ? g_h1s16 : g_h1p16;
    int cnt = g_cnt[t][n];
    int deg = min(cnt, CAP);
    const unsigned short* col = g_col[t] + (long)n*CAP;
    float ax = 0.f, ay = 0.f;
    int e = 0;
    int nd8 = deg & ~7;
    for (; e < nd8; e += 8) {
        uint4 cw = *(const uint4*)(col + e);
        int s[8];
        s[0] = cw.x & 0xffff; s[1] = cw.x >> 16;
        s[2] = cw.y & 0xffff; s[3] = cw.y >> 16;
        s[4] = cw.z & 0xffff; s[5] = cw.z >> 16;
        s[6] = cw.w & 0xffff; s[7] = cw.w >> 16;
        unsigned v[8];
#pragma unroll
        for (int q = 0; q < 8; q++)
            v[q] = *(const unsigned*)(src + (long)s[q]*HD + lane*2);
#pragma unroll
        for (int q = 0; q < 8; q++) {
            float2 f = __half22float2(*(const __half2*)&v[q]);
            ax += f.x; ay += f.y;
        }
    }
    for (; e < deg; e++) {
        unsigned v0 = *(const unsigned*)(src + (long)col[e]*HD + lane*2);
        float2 f = __half22float2(*(const __half2*)&v0);
        ax += f.x; ay += f.y;
    }
    float inv = 1.f / (float)max(cnt, 1);
    __half2 o = __floats2half2_rn(ax*inv, ay*inv);
    *(__half2*)(g_agg2[t] + (long)n*HD + lane*2) = o;
}

// ---------------- layer-1 GEMM: 128-row tile, single-pass K=48 -------------
struct G1Args {
    const __half *A0[2], *A1[2], *A2[2];   // each 50000 x 16 halves
    const __half *B[2];                    // 48 x 64
    const float  *bias[2];
    __half *C16[2];
};

#define A1STR 56
#define B1STR 72
#define C1STR 68

__global__ void gemm1_kernel(G1Args g) {
    __shared__ char smem[128*C1STR*4];     // 34816 B (epilogue dominates)
    __half* As = (__half*)smem;            // 128 x 56 halves = 14336 B
    __half* Bs = (__half*)(smem + 128*A1STR*2);  // 48 x 72 halves = 6912 B
    float*  Cs = (float*)smem;

    const int tid = threadIdx.x;
    const int ty  = blockIdx.y;
    const int m0  = blockIdx.x*128;
    const __half* Aseg[3] = {g.A0[ty], g.A1[ty], g.A2[ty]};
    const __half* B = g.B[ty];

    // stage A: 128 rows x 48 halves (3 segs of 16)
    for (int u = tid; u < 128*6; u += 256) {
        int m = u / 6;
        int h = (u - m*6) << 3;
        int seg = h >> 4, off = h & 15;
        int gm = m0 + m;
        float4 v = make_float4(0.f,0.f,0.f,0.f);
        if (gm < NN) v = *(const float4*)(Aseg[seg] + (long)gm*16 + off);
        *(float4*)(As + m*A1STR + h) = v;
    }
    // stage B: 48 rows x 64
    for (int u = tid; u < 48*8; u += 256) {
        int r = u >> 3, c = (u & 7) << 3;
        *(float4*)(Bs + r*B1STR + c) = *(const float4*)(B + (long)r*64 + c);
    }
    __syncthreads();

    wmma::fragment<wmma::matrix_a, 16,16,16, __half, wmma::row_major> af;
    wmma::fragment<wmma::matrix_b, 16,16,16, __half, wmma::row_major> bf;
    wmma::fragment<wmma::accumulator, 16,16,16, float> c[4];
#pragma unroll
    for (int j = 0; j < 4; j++) wmma::fill_fragment(c[j], 0.f);
    const int wr = tid >> 5;   // warp = 16-row group (0..7)
#pragma unroll
    for (int kc = 0; kc < 3; kc++) {
        wmma::load_matrix_sync(af, As + (wr*16)*A1STR + kc*16, A1STR);
#pragma unroll
        for (int j = 0; j < 4; j++) {
            wmma::load_matrix_sync(bf, Bs + (kc*16)*B1STR + j*16, B1STR);
            wmma::mma_sync(c[j], af, bf, c[j]);
        }
    }
    __syncthreads();
#pragma unroll
    for (int j = 0; j < 4; j++)
        wmma::store_matrix_sync(Cs + (wr*16)*C1STR + j*16, c[j], C1STR, wmma::mem_row_major);
    __syncthreads();

    const float* bias = g.bias[ty];
    int r = tid >> 1, lane = tid & 1;
    int gm = m0 + r;
    int cb = lane*32;
    if (gm < NN) {
        __half2 o[16];
#pragma unroll
        for (int j = 0; j < 16; j++) {
            float v0 = fmaxf(Cs[r*C1STR + cb + 2*j]   + bias[cb + 2*j],   0.f);
            float v1 = fmaxf(Cs[r*C1STR + cb + 2*j+1] + bias[cb + 2*j+1], 0.f);
            o[j] = __floats2half2_rn(v0, v1);
        }
        __half* dst = g.C16[ty] + (long)gm*HD + cb;
        *(float4*)dst        = *(float4*)&o[0];
        *(float4*)(dst + 8)  = *(float4*)&o[4];
        *(float4*)(dst + 16) = *(float4*)&o[8];
        *(float4*)(dst + 24) = *(float4*)&o[12];
    }
}

// ---------------- layer-2 GEMM: 128-row tile + fused final + cnt re-zero ---
struct G2Args {
    const __half *A0[2], *A1[2], *A2[2];   // each 50000 x 64
    const __half *B[2];                    // 192 x 64
    const float  *bias[2];
    const float  *wlin[2], *bfin[2];
    float *out[2];
};

#define A2STR 72
#define B2STR 72
#define C2STR 68

__global__ void gemm2_kernel(G2Args g) {
    __shared__ char smem[128*C2STR*4];     // 34816 B
    __half* As = (__half*)smem;            // 128 x 72 = 18432 B
    __half* Bs = (__half*)(smem + 128*A2STR*2);  // 64 x 72 = 9216 B
    float*  Cs = (float*)smem;

    const int tid = threadIdx.x;
    const int ty  = blockIdx.y;
    const int m0  = blockIdx.x*128;
    const __half* Aseg[3] = {g.A0[ty], g.A1[ty], g.A2[ty]};
    const __half* B = g.B[ty];

    wmma::fragment<wmma::matrix_a, 16,16,16, __half, wmma::row_major> af;
    wmma::fragment<wmma::matrix_b, 16,16,16, __half, wmma::row_major> bf;
    wmma::fragment<wmma::accumulator, 16,16,16, float> c[4];
#pragma unroll
    for (int j = 0; j < 4; j++) wmma::fill_fragment(c[j], 0.f);

    const int wr = tid >> 5;   // warp = 16-row group (0..7)

#pragma unroll 1
    for (int seg = 0; seg < 3; seg++) {
        __syncthreads();
        const __half* A = Aseg[seg];
        for (int u = tid; u < 128*8; u += 256) {
            int m = u >> 3;
            int h = (u & 7) << 3;
            int gm = m0 + m;
            float4 v = make_float4(0.f,0.f,0.f,0.f);
            if (gm < NN) v = *(const float4*)(A + (long)gm*HD + h);
            *(float4*)(As + m*A2STR + h) = v;
        }
        for (int u = tid; u < 64*8; u += 256) {
            int r = u >> 3, cc = (u & 7) << 3;
            *(float4*)(Bs + r*B2STR + cc) = *(const float4*)(B + (long)(seg*64 + r)*64 + cc);
        }
        __syncthreads();
#pragma unroll
        for (int kc = 0; kc < 4; kc++) {
            wmma::load_matrix_sync(af, As + (wr*16)*A2STR + kc*16, A2STR);
#pragma unroll
            for (int j = 0; j < 4; j++) {
                wmma::load_matrix_sync(bf, Bs + (kc*16)*B2STR + j*16, B2STR);
                wmma::mma_sync(c[j], af, bf, c[j]);
            }
        }
    }

    __syncthreads();
#pragma unroll
    for (int j = 0; j < 4; j++)
        wmma::store_matrix_sync(Cs + (wr*16)*C2STR + j*16, c[j], C2STR, wmma::mem_row_major);
    __syncthreads();

    // fused final: out[m] = relu(row + bias) . wlin + bfin
    const float* bias = g.bias[ty];
    const float* wl = g.wlin[ty];
    int r = tid >> 1, lane = tid & 1;
    int gm = m0 + r;
    int cb = lane*32;
    float s = 0.f;
#pragma unroll
    for (int cc = 0; cc < 32; cc++) {
        float v = fmaxf(Cs[r*C2STR + cb + cc] + bias[cb + cc], 0.f);
        s = fmaf(v, wl[cb + cc], s);
    }
    s += __shfl_xor_sync(0xffffffffu, s, 1, 2);
    if (lane == 0 && gm < NN) g.out[ty][gm] = s + g.bfin[ty][0];

    // self-clean: re-zero g_cnt for the next graph replay (stream-ordered;
    // nothing after gemm2 reads cnt within this replay).
    int zi = (blockIdx.y*gridDim.x + blockIdx.x)*blockDim.x + threadIdx.x;
    if (zi < 4*NN) ((int*)g_cnt)[zi] = 0;
}

// ---------------- launch ----------------
extern "C" void kernel_launch(void* const* d_in, const int* in_sizes, int n_in,
                              void* d_out, int out_size) {
    (void)in_sizes; (void)n_in; (void)out_size;
    const float* x_shop = (const float*)d_in[0];
    const float* x_pub  = (const float*)d_in[1];
    const float* w1_l   = (const float*)d_in[2];
    const float* b1_l   = (const float*)d_in[3];
    const float* w1_r   = (const float*)d_in[4];
    const float* w2_l   = (const float*)d_in[5];
    const float* b2_l   = (const float*)d_in[6];
    const float* w2_r   = (const float*)d_in[7];
    const float* wls    = (const float*)d_in[8];
    const float* bls    = (const float*)d_in[9];
    const float* wlp    = (const float*)d_in[10];
    const float* blp    = (const float*)d_in[11];
    const int* ei_ss    = (const int*)d_in[12];
    const int* ei_sp    = (const int*)d_in[13];
    const int* ei_ps    = (const int*)d_in[14];
    const int* ei_pp    = (const int*)d_in[15];

    __half *agg1, *agg2, *h1s16, *h1p16, *x16, *wb1, *wb2;
    float *b1, *b2;
    cudaGetSymbolAddress((void**)&agg1, g_agg1);
    cudaGetSymbolAddress((void**)&agg2, g_agg2);
    cudaGetSymbolAddress((void**)&h1s16, g_h1s16);
    cudaGetSymbolAddress((void**)&h1p16, g_h1p16);
    cudaGetSymbolAddress((void**)&x16,  g_x16);
    cudaGetSymbolAddress((void**)&wb1,  g_wb1);
    cudaGetSymbolAddress((void**)&wb2,  g_wb2);
    cudaGetSymbolAddress((void**)&b1,   g_b1);
    cudaGetSymbolAddress((void**)&b2,   g_b2);

    const int TB = 256;
    const int GB2 = (NN + 127) / 128;             // 391
    float* out = (float*)d_out;

    prep_place_kernel<<<PBLK + QBLK, TB>>>(x_shop, x_pub, w1_l, w1_r, w2_l, w2_r,
                                           b1_l, b2_l, ei_ss, ei_sp, ei_ps, ei_pp);

    // ---- layer 1 ----
    gather1_kernel<<<(4*NN + 15)/16, TB>>>();
    {
        G1Args a;
        a.A0[0] = agg1 + 0L*N16;  a.A0[1] = agg1 + 1L*N16;
        a.A1[0] = agg1 + 2L*N16;  a.A1[1] = agg1 + 3L*N16;
        a.A2[0] = x16 + 0L*N16;   a.A2[1] = x16 + 1L*N16;
        a.B[0] = wb1;             a.B[1] = wb1 + 48*64;
        a.bias[0] = b1;           a.bias[1] = b1 + HD;
        a.C16[0] = h1s16;         a.C16[1] = h1p16;
        gemm1_kernel<<<dim3(GB2,2), TB>>>(a);
    }

    // ---- layer 2 ----
    gather2_kernel<<<(4*NN + 7)/8, TB>>>();
    {
        G2Args a;
        a.A0[0] = agg2 + 0L*N64;  a.A0[1] = agg2 + 1L*N64;
        a.A1[0] = agg2 + 2L*N64;  a.A1[1] = agg2 + 3L*N64;
        a.A2[0] = h1s16;          a.A2[1] = h1p16;
        a.B[0] = wb2;             a.B[1] = wb2 + 192*64;
        a.bias[0] = b2;           a.bias[1] = b2 + HD;
        a.wlin[0] = wls;          a.wlin[1] = wlp;
        a.bfin[0] = bls;          a.bfin[1] = blp;
        a.out[0] = out;           a.out[1] = out + NN;
        gemm2_kernel<<<dim3(GB2,2), TB>>>(a);
    }
}